// round 4
// baseline (speedup 1.0000x reference)
#include <cuda_runtime.h>
#include <cuda_bf16.h>
#include <math.h>

#define H      256
#define HE     64
#define APER   64
#define NPER   512
#define EPSF   1e-8f
#define INFM   1000000.0f
#define MU_STEP (20.0f/63.0f)
#define INV_SIG (64.0f/20.0f)

// ------------------------- scratch (device globals) --------------------------
__device__ float g_wc [256*320];   // Wq^T @ Wkv[:, :320]
__device__ float g_aux[640];       // [0:256) wqbk, [256:576) biasc, [576] bqbk
__device__ float g_qke[512*320];
__device__ float g_cb [512*320];   // [n_tilde | s]
__device__ float g_upd[512*256];
__device__ float g_af [512*256];
__device__ float g_m1 [512*512];
__device__ float g_m2 [512*512];
__device__ float g_m3 [512*256];

// ------------------------- utils ---------------------------------------------
__device__ __forceinline__ float warp_reduce_sum(float v){
#pragma unroll
  for (int o=16;o>0;o>>=1) v += __shfl_xor_sync(0xffffffffu, v, o);
  return v;
}
__device__ __forceinline__ float warp_reduce_max(float v){
#pragma unroll
  for (int o=16;o>0;o>>=1) v = fmaxf(v, __shfl_xor_sync(0xffffffffu, v, o));
  return v;
}

// ------------------------- GEMM v2: double-buffered, prefetched --------------
// C[M,N] = act(A @ op(B) + bias). Tile BM x 64, 128 threads.
// A_KM: A stored K-major (A[k*lda+m]) else row-major (A[m*lda+k]).
// B_KN: B is (K,N) row-major, else (N,K) row-major.
// VEC:  last blockIdx.x column (y==0) computes aux vectors instead of a tile.
template<int BM, bool A_KM, bool B_KN, bool BIAS, bool RELU, bool VEC>
__global__ __launch_bounds__(128)
void gemm2(const float* __restrict__ A, int lda,
           const float* __restrict__ B, int ldb,
           const float* __restrict__ bias,
           float* __restrict__ C, int ldc,
           int M, int N, int K,
           const float* __restrict__ vbq,
           const float* __restrict__ vbk,
           float* __restrict__ vaux)
{
  if (VEC && blockIdx.x == gridDim.x - 1){
    if (blockIdx.y) return;
    const int t = threadIdx.x;
    // wqbk[i] = sum_j Wq[j][i] * bk[j]   (A = Wq, K-major, lda)
    for (int i = t; i < 256; i += 128){
      float s = 0.f;
#pragma unroll 4
      for (int j = 0; j < 256; j++) s = fmaf(A[(size_t)j*lda + i], vbk[j], s);
      vaux[i] = s;
    }
    // biasc[c] = sum_j bq[j] * Wkv[j][c]
    for (int c = t; c < 320; c += 128){
      float s = 0.f;
#pragma unroll 4
      for (int j = 0; j < 256; j++) s = fmaf(vbq[j], B[(size_t)j*ldb + c], s);
      vaux[256 + c] = s;
    }
    if (t == 0){
      float s = 0.f;
      for (int j = 0; j < 256; j++) s = fmaf(vbq[j], vbk[j], s);
      vaux[576] = s;
    }
    return;
  }

  constexpr int RM = BM / 8;
  __shared__ __align__(16) float As[2][16][36];
  __shared__ __align__(16) float Bs[2][16][68];

  const int tid = threadIdx.x;
  const int tx = tid & 15, ty = tid >> 4;
  const int m0 = blockIdx.y * BM, n0 = blockIdx.x * 64;

  float acc[RM][4];
#pragma unroll
  for (int i=0;i<RM;i++)
#pragma unroll
    for (int j=0;j<4;j++) acc[i][j] = 0.f;

  // ---- initial tile -> buffer 0 ----
  {
    float4 pa; bool apart = true; int ar=0, ak=0;
    if (A_KM){
      const int cnt = 4*BM;              // float4 count (16 kk x BM/4)
      apart = (tid < cnt);
      if (apart){ ak = tid / (BM/4); ar = tid % (BM/4);
        pa = *(const float4*)(A + (size_t)(0 + ak)*lda + m0 + ar*4); }
    } else {
      apart = (BM == 32) || (tid < 64);
      if (apart){ ar = tid >> 2; ak = tid & 3;
        pa = *(const float4*)(A + (size_t)(m0 + ar)*lda + 0 + ak*4); }
    }
    float4 pb[2]; int bn[2], bk[2];
#pragma unroll
    for (int q=0;q<2;q++){
      int e = tid + q*128;
      if (B_KN){ bk[q] = e >> 4; bn[q] = e & 15;
        pb[q] = *(const float4*)(B + (size_t)(0 + bk[q])*ldb + n0 + bn[q]*4);
      } else {   bn[q] = e >> 2; bk[q] = e & 3;
        pb[q] = *(const float4*)(B + (size_t)(n0 + bn[q])*ldb + 0 + bk[q]*4); }
    }
    if (apart){
      if (A_KM) *(float4*)&As[0][ak][ar*4] = pa;
      else { As[0][ak*4+0][ar]=pa.x; As[0][ak*4+1][ar]=pa.y;
             As[0][ak*4+2][ar]=pa.z; As[0][ak*4+3][ar]=pa.w; }
    }
#pragma unroll
    for (int q=0;q<2;q++){
      if (B_KN) *(float4*)&Bs[0][bk[q]][bn[q]*4] = pb[q];
      else { Bs[0][bk[q]*4+0][bn[q]]=pb[q].x; Bs[0][bk[q]*4+1][bn[q]]=pb[q].y;
             Bs[0][bk[q]*4+2][bn[q]]=pb[q].z; Bs[0][bk[q]*4+3][bn[q]]=pb[q].w; }
    }
  }
  __syncthreads();

  int buf = 0;
  for (int k0 = 16; ; k0 += 16, buf ^= 1){
    const bool more = (k0 < K);
    float4 pa; bool apart = true; int ar=0, ak=0;
    float4 pb[2]; int bn[2], bk[2];
    if (more){
      if (A_KM){
        const int cnt = 4*BM;
        apart = (tid < cnt);
        if (apart){ ak = tid / (BM/4); ar = tid % (BM/4);
          pa = *(const float4*)(A + (size_t)(k0 + ak)*lda + m0 + ar*4); }
      } else {
        apart = (BM == 32) || (tid < 64);
        if (apart){ ar = tid >> 2; ak = tid & 3;
          pa = *(const float4*)(A + (size_t)(m0 + ar)*lda + k0 + ak*4); }
      }
#pragma unroll
      for (int q=0;q<2;q++){
        int e = tid + q*128;
        if (B_KN){ bk[q] = e >> 4; bn[q] = e & 15;
          pb[q] = *(const float4*)(B + (size_t)(k0 + bk[q])*ldb + n0 + bn[q]*4);
        } else {   bn[q] = e >> 2; bk[q] = e & 3;
          pb[q] = *(const float4*)(B + (size_t)(n0 + bn[q])*ldb + k0 + bk[q]*4); }
      }
    }
    // ---- compute on current buffer ----
#pragma unroll
    for (int kk = 0; kk < 16; kk++){
      float4 bv = *(const float4*)&Bs[buf][kk][tx*4];
      float bb[4] = {bv.x, bv.y, bv.z, bv.w};
      if (RM == 4){
        float4 av = *(const float4*)&As[buf][kk][ty*4];
        float aa[4] = {av.x, av.y, av.z, av.w};
#pragma unroll
        for (int i=0;i<4;i++)
#pragma unroll
          for (int j=0;j<4;j++) acc[i][j] = fmaf(aa[i], bb[j], acc[i][j]);
      } else {
        float a0 = As[buf][kk][ty*2+0];
        float a1 = As[buf][kk][ty*2+1];
#pragma unroll
        for (int j=0;j<4;j++){
          acc[0][j] = fmaf(a0, bb[j], acc[0][j]);
          acc[1][j] = fmaf(a1, bb[j], acc[1][j]);
        }
      }
    }
    if (!more) break;
    // ---- stage prefetched regs into other buffer ----
    if (apart){
      if (A_KM) *(float4*)&As[buf^1][ak][ar*4] = pa;
      else { As[buf^1][ak*4+0][ar]=pa.x; As[buf^1][ak*4+1][ar]=pa.y;
             As[buf^1][ak*4+2][ar]=pa.z; As[buf^1][ak*4+3][ar]=pa.w; }
    }
#pragma unroll
    for (int q=0;q<2;q++){
      if (B_KN) *(float4*)&Bs[buf^1][bk[q]][bn[q]*4] = pb[q];
      else { Bs[buf^1][bk[q]*4+0][bn[q]]=pb[q].x; Bs[buf^1][bk[q]*4+1][bn[q]]=pb[q].y;
             Bs[buf^1][bk[q]*4+2][bn[q]]=pb[q].z; Bs[buf^1][bk[q]*4+3][bn[q]]=pb[q].w; }
    }
    __syncthreads();
  }

  // ---- epilogue ----
#pragma unroll
  for (int i=0;i<RM;i++){
    const int m = m0 + ty*RM + i;
    float4 v = make_float4(acc[i][0], acc[i][1], acc[i][2], acc[i][3]);
    if (BIAS){
      const float4 bv = *(const float4*)(bias + n0 + tx*4);
      v.x += bv.x; v.y += bv.y; v.z += bv.z; v.w += bv.w;
    }
    if (RELU){
      v.x = fmaxf(v.x,0.f); v.y = fmaxf(v.y,0.f);
      v.z = fmaxf(v.z,0.f); v.w = fmaxf(v.w,0.f);
    }
    *(float4*)(C + (size_t)m*ldc + n0 + tx*4) = v;
  }
}

// ------------------------- fused attention -----------------------------------
// Block = 4 anchors of one batch, 512 threads. Writes cbuf=[n_tilde|s] (512x320).
__global__ __launch_bounds__(512)
void attn_kernel(const float* __restrict__ anchor_x,
                 const float* __restrict__ node_x,
                 const float* __restrict__ nmask,
                 const float* __restrict__ nf,
                 const float* __restrict__ afeat,
                 const float* __restrict__ aux,   // wqbk | biasc | bqbk
                 const float* __restrict__ qke,   // 512x320
                 float* __restrict__ cbuf)
{
  const int tid  = threadIdx.x;
  const int lane = tid & 31, warp = tid >> 5;
  const int a0   = blockIdx.x * 4;
  const int b    = a0 / APER;
  const int nbase = b * NPER;

  __shared__ __align__(16) float qk_s [4][H];
  __shared__ __align__(16) float qek_s[4][HE];
  __shared__ __align__(16) float dist_s[4][NPER];
  __shared__ __align__(16) float logit_s[4][NPER];
  __shared__ float ax_s[4][3];
  __shared__ float qbk_s[4];
  __shared__ int   list_s[NPER];
  __shared__ int   cnt_s;
  __shared__ float red_s[16];

  if (tid == 0) cnt_s = 0;
  for (int i = tid; i < 4*320; i += 512){
    int r = i / 320, c = i - r*320;
    float v = qke[(size_t)(a0 + r)*320 + c];
    if (c < 256) qk_s[r][c] = v; else qek_s[r][c-256] = v;
  }
  if (tid < 12) ax_s[tid/3][tid%3] = anchor_x[(size_t)(a0 + tid/3)*3 + (tid%3)];
  __syncthreads();

  // ---- Phase A: distances, zero logits, masked-node compaction ---------------
  {
    const int n = tid, ng = nbase + n;
    const float x0 = node_x[(size_t)3*ng+0];
    const float x1 = node_x[(size_t)3*ng+1];
    const float x2 = node_x[(size_t)3*ng+2];
#pragma unroll
    for (int a=0;a<4;a++){
      float dx = ax_s[a][0]-x0+EPSF;
      float dy = ax_s[a][1]-x1+EPSF;
      float dz = ax_s[a][2]-x2+EPSF;
      dist_s[a][n] = sqrtf(dx*dx + dy*dy + dz*dz);
      logit_s[a][n] = 0.0f;
    }
    if (nmask[ng] == 0.0f){
      int p = atomicAdd(&cnt_s, 1);
      list_s[p] = n;
    }
  }
  // qbk[a] = afeat[a] . wqbk + bqbk
  if (warp < 4){
    const float* ar = afeat + (size_t)(a0 + warp)*H;
    float s = 0.f;
#pragma unroll
    for (int kk=0;kk<8;kk++) s = fmaf(ar[lane + kk*32], aux[lane + kk*32], s);
    s = warp_reduce_sum(s);
    if (lane == 0) qbk_s[warp] = s + aux[576];
  }
  __syncthreads();

  // ---- Phase A2: logits for masked nodes only --------------------------------
  {
    const int cnt = cnt_s;
    const float mu0 = (float)lane * MU_STEP;
    const float mu1 = (float)(lane+32) * MU_STEP;
    for (int i = warp; i < cnt; i += 16){
      const int n = list_s[i], ng = nbase + n;
      const float4* nf4 = (const float4*)(nf + (size_t)ng*H);
      float4 u0 = nf4[lane], u1 = nf4[lane+32];
#pragma unroll
      for (int a=0;a<4;a++){
        float t = dist_s[a][n] * 0.1f;
        float z0 = (t - mu0) * INV_SIG, z1 = (t - mu1) * INV_SIG;
        float z0s = z0*z0, z1s = z1*z1;
        float acc = 0.f;
        if (z0s < 64.f) acc  = __expf(-z0s) * qek_s[a][lane];
        if (z1s < 64.f) acc += __expf(-z1s) * qek_s[a][lane+32];
        const float4* qa = (const float4*)qk_s[a];
        float4 q0 = qa[lane], q1 = qa[lane+32];
        acc = fmaf(u0.x,q0.x, fmaf(u0.y,q0.y, fmaf(u0.z,q0.z, fmaf(u0.w,q0.w, acc))));
        acc = fmaf(u1.x,q1.x, fmaf(u1.y,q1.y, fmaf(u1.z,q1.z, fmaf(u1.w,q1.w, acc))));
        acc = warp_reduce_sum(acc);
        if (lane == 0) logit_s[a][n] = (acc + qbk_s[a]) * (-INFM);
      }
    }
  }
  __syncthreads();

  // ---- Phase B: softmax over 512 nodes per anchor -----------------------------
#pragma unroll
  for (int a=0;a<4;a++){
    float l = logit_s[a][tid];
    float wm = warp_reduce_max(l);
    __syncthreads();
    if (lane == 0) red_s[warp] = wm;
    __syncthreads();
    float mx = red_s[0];
#pragma unroll
    for (int k=1;k<16;k++) mx = fmaxf(mx, red_s[k]);
    float e = __expf(l - mx);
    float ws = warp_reduce_sum(e);
    __syncthreads();
    if (lane == 0) red_s[warp] = ws;
    __syncthreads();
    float sm = red_s[0];
#pragma unroll
    for (int k=1;k<16;k++) sm += red_s[k];
    logit_s[a][tid] = e / sm;
  }
  __syncthreads();

  // ---- Phase C1: s[a][j] = sum_n attn * rbf -----------------------------------
  {
    const int a = tid >> 7, r = tid & 127, j = r >> 1, half = r & 1;
    const float mu = (float)j * MU_STEP;
    float acc = 0.f;
    const int nb0 = half * 256;
#pragma unroll 4
    for (int nn=0; nn<256; nn++){
      int n = nb0 + nn;
      float z = (dist_s[a][n]*0.1f - mu) * INV_SIG;
      float z2 = z*z;
      if (z2 < 60.f) acc = fmaf(logit_s[a][n], __expf(-z2), acc);
    }
    acc += __shfl_xor_sync(0xffffffffu, acc, 1);
    if (half == 0) cbuf[(size_t)(a0+a)*320 + 256 + j] = acc;
  }
  __syncthreads();

  // ---- Phase C2: n_tilde[a][i] = sum_n attn * nf[n][i] ------------------------
  {
    const int i = tid & 255, g = tid >> 8;
    float ac0=0.f, ac1=0.f, ac2=0.f, ac3=0.f;
    const float* nfb = nf + (size_t)(nbase + g*256)*H + i;
    const int nb0 = g*256;
    for (int nn=0; nn<256; nn+=4){
      float4 w0 = *(const float4*)&logit_s[0][nb0+nn];
      float4 w1 = *(const float4*)&logit_s[1][nb0+nn];
      float4 w2 = *(const float4*)&logit_s[2][nb0+nn];
      float4 w3 = *(const float4*)&logit_s[3][nb0+nn];
      float f0 = nfb[(size_t)(nn+0)*H];
      float f1 = nfb[(size_t)(nn+1)*H];
      float f2 = nfb[(size_t)(nn+2)*H];
      float f3 = nfb[(size_t)(nn+3)*H];
      ac0 = fmaf(w0.x,f0, fmaf(w0.y,f1, fmaf(w0.z,f2, fmaf(w0.w,f3, ac0))));
      ac1 = fmaf(w1.x,f0, fmaf(w1.y,f1, fmaf(w1.z,f2, fmaf(w1.w,f3, ac1))));
      ac2 = fmaf(w2.x,f0, fmaf(w2.y,f1, fmaf(w2.z,f2, fmaf(w2.w,f3, ac2))));
      ac3 = fmaf(w3.x,f0, fmaf(w3.y,f1, fmaf(w3.z,f2, fmaf(w3.w,f3, ac3))));
    }
    __syncthreads();
    if (g == 1){
      dist_s[0][i]=ac0; dist_s[1][i]=ac1; dist_s[2][i]=ac2; dist_s[3][i]=ac3;
    }
    __syncthreads();
    if (g == 0){
      cbuf[(size_t)(a0+0)*320 + i] = ac0 + dist_s[0][i];
      cbuf[(size_t)(a0+1)*320 + i] = ac1 + dist_s[1][i];
      cbuf[(size_t)(a0+2)*320 + i] = ac2 + dist_s[2][i];
      cbuf[(size_t)(a0+3)*320 + i] = ac3 + dist_s[3][i];
    }
  }
}

// ------------------------- residual + LayerNorm -------------------------------
__global__ void ln_kernel(const float* __restrict__ r,
                          const float* __restrict__ y1,
                          const float* __restrict__ g,
                          const float* __restrict__ bb,
                          float* __restrict__ out)
{
  __shared__ float red[8];
  const int row = blockIdx.x, t = threadIdx.x, lane = t & 31, w = t >> 5;
  const size_t o = (size_t)row*H + t;
  float x = r[o] + y1[o];
  float s = warp_reduce_sum(x);
  if (lane == 0) red[w] = s;
  __syncthreads();
  float mean = (red[0]+red[1]+red[2]+red[3]+red[4]+red[5]+red[6]+red[7]) * (1.f/H);
  float d = x - mean;
  float s2 = warp_reduce_sum(d*d);
  __syncthreads();
  if (lane == 0) red[w] = s2;
  __syncthreads();
  float var = (red[0]+red[1]+red[2]+red[3]+red[4]+red[5]+red[6]+red[7]) * (1.f/H);
  out[o] = d * rsqrtf(var + 1e-5f) * g[t] + bb[t];
}

// ------------------------- launch ---------------------------------------------
extern "C" void kernel_launch(void* const* d_in, const int* in_sizes, int n_in,
                              void* d_out, int out_size)
{
  const float* anchor_x        = (const float*)d_in[0];
  const float* node_x          = (const float*)d_in[1];
  const float* anchor_features = (const float*)d_in[2];
  const float* node_features   = (const float*)d_in[3];
  const float* node_mask       = (const float*)d_in[6];
  const float* Wq              = (const float*)d_in[7];
  const float* bq              = (const float*)d_in[8];
  const float* Wkv             = (const float*)d_in[9];
  const float* bkv             = (const float*)d_in[10];
  const float* ln1_g           = (const float*)d_in[11];
  const float* ln1_b           = (const float*)d_in[12];
  const float* W1              = (const float*)d_in[13];
  const float* b1              = (const float*)d_in[14];
  const float* W2              = (const float*)d_in[15];
  const float* b2              = (const float*)d_in[16];
  const float* W3              = (const float*)d_in[17];
  const float* b3              = (const float*)d_in[18];
  const float* ln2_g           = (const float*)d_in[19];
  const float* ln2_b           = (const float*)d_in[20];
  float* out = (float*)d_out;

  float *pwc, *paux, *pqke, *pcb, *pupd, *paf, *pm1, *pm2, *pm3;
  cudaGetSymbolAddress((void**)&pwc,  g_wc);
  cudaGetSymbolAddress((void**)&paux, g_aux);
  cudaGetSymbolAddress((void**)&pqke, g_qke);
  cudaGetSymbolAddress((void**)&pcb,  g_cb);
  cudaGetSymbolAddress((void**)&pupd, g_upd);
  cudaGetSymbolAddress((void**)&paf,  g_af);
  cudaGetSymbolAddress((void**)&pm1,  g_m1);
  cudaGetSymbolAddress((void**)&pm2,  g_m2);
  cudaGetSymbolAddress((void**)&pm3,  g_m3);

  // 1) Wc = Wq^T @ Wkv[:, :320]  (+ aux vectors in the spare block column)
  gemm2<16,true,true,false,false,true><<<dim3(6,16), 128>>>(
      Wq, 256, Wkv, 320, nullptr, pwc, 320, 256, 320, 256, bq, bkv, paux);

  // 2) qke = anchor_features @ Wc + biasc       (512 x 320, K=256)
  gemm2<16,false,true,true,false,false><<<dim3(5,32), 128>>>(
      anchor_features, 256, pwc, 320, paux + 256, pqke, 320, 512, 320, 256,
      nullptr, nullptr, nullptr);

  // 3) fused attention -> cbuf = [n_tilde | s]
  attn_kernel<<<128, 512>>>(anchor_x, node_x, node_mask, node_features,
                            anchor_features, paux, pqke, pcb);

  // 4) upd = cbuf @ Wkv[256:512,:].T + bkv[256:]  (512 x 256, K=320)
  gemm2<16,false,false,true,false,false><<<dim3(4,32), 128>>>(
      pcb, 320, Wkv + (size_t)256*320, 320, bkv + 256, pupd, 256, 512, 256, 320,
      nullptr, nullptr, nullptr);

  // 5) af = LN1(anchor_features + upd)
  ln_kernel<<<512, 256>>>(anchor_features, pupd, ln1_g, ln1_b, paf);

  // 6) m1 = relu(af @ W1.T + b1)                 (512 x 512, K=256)
  gemm2<16,false,false,true,true,false><<<dim3(8,32), 128>>>(
      paf, 256, W1, 256, b1, pm1, 512, 512, 512, 256,
      nullptr, nullptr, nullptr);

  // 7) m2 = relu(m1 @ W2.T + b2)                 (512 x 512, K=512)
  gemm2<16,false,false,true,true,false><<<dim3(8,32), 128>>>(
      pm1, 512, W2, 512, b2, pm2, 512, 512, 512, 512,
      nullptr, nullptr, nullptr);

  // 8) m3 = m2 @ W3.T + b3                       (512 x 256, K=512)
  gemm2<16,false,false,true,false,false><<<dim3(4,32), 128>>>(
      pm2, 512, W3, 512, b3, pm3, 256, 512, 256, 512,
      nullptr, nullptr, nullptr);

  // 9) out = LN2(af + m3)
  ln_kernel<<<512, 256>>>(paf, pm3, ln2_g, ln2_b, out);
}

// round 5
// speedup vs baseline: 1.0017x; 1.0017x over previous
#include <cuda_runtime.h>
#include <cuda_bf16.h>
#include <math.h>

#define H      256
#define HE     64
#define APER   64
#define NPER   512
#define EPSF   1e-8f
#define INFM   1000000.0f
#define MU_STEP (20.0f/63.0f)
#define INV_SIG (64.0f/20.0f)

// ------------------------- scratch (device globals) --------------------------
__device__ float g_wc [256*320];   // Wq^T @ Wkv[:, :320]
__device__ float g_aux[640];       // [0:256) wqbk, [256:576) biasc, [576] bqbk
__device__ float g_qke[512*320];
__device__ float g_cb [512*320];   // [n_tilde | s]
__device__ float g_upd[512*256];
__device__ float g_af [512*256];
__device__ float g_m1 [512*512];
__device__ float g_m2 [512*512];
__device__ float g_m3 [512*256];

// ------------------------- utils ---------------------------------------------
__device__ __forceinline__ float warp_reduce_sum(float v){
#pragma unroll
  for (int o=16;o>0;o>>=1) v += __shfl_xor_sync(0xffffffffu, v, o);
  return v;
}
__device__ __forceinline__ float warp_reduce_max(float v){
#pragma unroll
  for (int o=16;o>0;o>>=1) v = fmaxf(v, __shfl_xor_sync(0xffffffffu, v, o));
  return v;
}

// ------------------------- GEMM v2: double-buffered, prefetched --------------
// C[M,N] = act(A @ op(B) + bias). Tile BM x 64, 128 threads.
// A_KM: A stored K-major (A[k*lda+m]) else row-major (A[m*lda+k]).
// B_KN: B is (K,N) row-major, else (N,K) row-major.
// VEC:  last blockIdx.x column (y==0) computes aux vectors instead of a tile.
template<int BM, bool A_KM, bool B_KN, bool BIAS, bool RELU, bool VEC>
__global__ __launch_bounds__(128)
void gemm2(const float* __restrict__ A, int lda,
           const float* __restrict__ B, int ldb,
           const float* __restrict__ bias,
           float* __restrict__ C, int ldc,
           int M, int N, int K,
           const float* __restrict__ vbq,
           const float* __restrict__ vbk,
           float* __restrict__ vaux)
{
  if (VEC && blockIdx.x == gridDim.x - 1){
    if (blockIdx.y) return;
    const int t = threadIdx.x;
    // wqbk[i] = sum_j Wq[j][i] * bk[j]   (A = Wq, K-major, lda)
    for (int i = t; i < 256; i += 128){
      float s = 0.f;
#pragma unroll 4
      for (int j = 0; j < 256; j++) s = fmaf(A[(size_t)j*lda + i], vbk[j], s);
      vaux[i] = s;
    }
    // biasc[c] = sum_j bq[j] * Wkv[j][c]
    for (int c = t; c < 320; c += 128){
      float s = 0.f;
#pragma unroll 4
      for (int j = 0; j < 256; j++) s = fmaf(vbq[j], B[(size_t)j*ldb + c], s);
      vaux[256 + c] = s;
    }
    if (t == 0){
      float s = 0.f;
      for (int j = 0; j < 256; j++) s = fmaf(vbq[j], vbk[j], s);
      vaux[576] = s;
    }
    return;
  }

  constexpr int RM = BM / 8;
  __shared__ __align__(16) float As[2][16][36];
  __shared__ __align__(16) float Bs[2][16][68];

  const int tid = threadIdx.x;
  const int tx = tid & 15, ty = tid >> 4;
  const int m0 = blockIdx.y * BM, n0 = blockIdx.x * 64;

  float acc[RM][4];
#pragma unroll
  for (int i=0;i<RM;i++)
#pragma unroll
    for (int j=0;j<4;j++) acc[i][j] = 0.f;

  // ---- initial tile -> buffer 0 ----
  {
    float4 pa; bool apart = true; int ar=0, ak=0;
    if (A_KM){
      const int cnt = 4*BM;              // float4 count (16 kk x BM/4)
      apart = (tid < cnt);
      if (apart){ ak = tid / (BM/4); ar = tid % (BM/4);
        pa = *(const float4*)(A + (size_t)(0 + ak)*lda + m0 + ar*4); }
    } else {
      apart = (BM == 32) || (tid < 64);
      if (apart){ ar = tid >> 2; ak = tid & 3;
        pa = *(const float4*)(A + (size_t)(m0 + ar)*lda + 0 + ak*4); }
    }
    float4 pb[2]; int bn[2], bk[2];
#pragma unroll
    for (int q=0;q<2;q++){
      int e = tid + q*128;
      if (B_KN){ bk[q] = e >> 4; bn[q] = e & 15;
        pb[q] = *(const float4*)(B + (size_t)(0 + bk[q])*ldb + n0 + bn[q]*4);
      } else {   bn[q] = e >> 2; bk[q] = e & 3;
        pb[q] = *(const float4*)(B + (size_t)(n0 + bn[q])*ldb + 0 + bk[q]*4); }
    }
    if (apart){
      if (A_KM) *(float4*)&As[0][ak][ar*4] = pa;
      else { As[0][ak*4+0][ar]=pa.x; As[0][ak*4+1][ar]=pa.y;
             As[0][ak*4+2][ar]=pa.z; As[0][ak*4+3][ar]=pa.w; }
    }
#pragma unroll
    for (int q=0;q<2;q++){
      if (B_KN) *(float4*)&Bs[0][bk[q]][bn[q]*4] = pb[q];
      else { Bs[0][bk[q]*4+0][bn[q]]=pb[q].x; Bs[0][bk[q]*4+1][bn[q]]=pb[q].y;
             Bs[0][bk[q]*4+2][bn[q]]=pb[q].z; Bs[0][bk[q]*4+3][bn[q]]=pb[q].w; }
    }
  }
  __syncthreads();

  int buf = 0;
  for (int k0 = 16; ; k0 += 16, buf ^= 1){
    const bool more = (k0 < K);
    float4 pa; bool apart = true; int ar=0, ak=0;
    float4 pb[2]; int bn[2], bk[2];
    if (more){
      if (A_KM){
        const int cnt = 4*BM;
        apart = (tid < cnt);
        if (apart){ ak = tid / (BM/4); ar = tid % (BM/4);
          pa = *(const float4*)(A + (size_t)(k0 + ak)*lda + m0 + ar*4); }
      } else {
        apart = (BM == 32) || (tid < 64);
        if (apart){ ar = tid >> 2; ak = tid & 3;
          pa = *(const float4*)(A + (size_t)(m0 + ar)*lda + k0 + ak*4); }
      }
#pragma unroll
      for (int q=0;q<2;q++){
        int e = tid + q*128;
        if (B_KN){ bk[q] = e >> 4; bn[q] = e & 15;
          pb[q] = *(const float4*)(B + (size_t)(k0 + bk[q])*ldb + n0 + bn[q]*4);
        } else {   bn[q] = e >> 2; bk[q] = e & 3;
          pb[q] = *(const float4*)(B + (size_t)(n0 + bn[q])*ldb + k0 + bk[q]*4); }
      }
    }
    // ---- compute on current buffer ----
#pragma unroll
    for (int kk = 0; kk < 16; kk++){
      float4 bv = *(const float4*)&Bs[buf][kk][tx*4];
      float bb[4] = {bv.x, bv.y, bv.z, bv.w};
      if (RM == 4){
        float4 av = *(const float4*)&As[buf][kk][ty*4];
        float aa[4] = {av.x, av.y, av.z, av.w};
#pragma unroll
        for (int i=0;i<4;i++)
#pragma unroll
          for (int j=0;j<4;j++) acc[i][j] = fmaf(aa[i], bb[j], acc[i][j]);
      } else {
        float a0 = As[buf][kk][ty*2+0];
        float a1 = As[buf][kk][ty*2+1];
#pragma unroll
        for (int j=0;j<4;j++){
          acc[0][j] = fmaf(a0, bb[j], acc[0][j]);
          acc[1][j] = fmaf(a1, bb[j], acc[1][j]);
        }
      }
    }
    if (!more) break;
    // ---- stage prefetched regs into other buffer ----
    if (apart){
      if (A_KM) *(float4*)&As[buf^1][ak][ar*4] = pa;
      else { As[buf^1][ak*4+0][ar]=pa.x; As[buf^1][ak*4+1][ar]=pa.y;
             As[buf^1][ak*4+2][ar]=pa.z; As[buf^1][ak*4+3][ar]=pa.w; }
    }
#pragma unroll
    for (int q=0;q<2;q++){
      if (B_KN) *(float4*)&Bs[buf^1][bk[q]][bn[q]*4] = pb[q];
      else { Bs[buf^1][bk[q]*4+0][bn[q]]=pb[q].x; Bs[buf^1][bk[q]*4+1][bn[q]]=pb[q].y;
             Bs[buf^1][bk[q]*4+2][bn[q]]=pb[q].z; Bs[buf^1][bk[q]*4+3][bn[q]]=pb[q].w; }
    }
    __syncthreads();
  }

  // ---- epilogue ----
#pragma unroll
  for (int i=0;i<RM;i++){
    const int m = m0 + ty*RM + i;
    float4 v = make_float4(acc[i][0], acc[i][1], acc[i][2], acc[i][3]);
    if (BIAS){
      const float4 bv = *(const float4*)(bias + n0 + tx*4);
      v.x += bv.x; v.y += bv.y; v.z += bv.z; v.w += bv.w;
    }
    if (RELU){
      v.x = fmaxf(v.x,0.f); v.y = fmaxf(v.y,0.f);
      v.z = fmaxf(v.z,0.f); v.w = fmaxf(v.w,0.f);
    }
    *(float4*)(C + (size_t)m*ldc + n0 + tx*4) = v;
  }
}

// ------------------------- fused attention -----------------------------------
// Block = 4 anchors of one batch, 512 threads. Writes cbuf=[n_tilde|s] (512x320).
__global__ __launch_bounds__(512)
void attn_kernel(const float* __restrict__ anchor_x,
                 const float* __restrict__ node_x,
                 const float* __restrict__ nmask,
                 const float* __restrict__ nf,
                 const float* __restrict__ afeat,
                 const float* __restrict__ aux,   // wqbk | biasc | bqbk
                 const float* __restrict__ qke,   // 512x320
                 float* __restrict__ cbuf)
{
  const int tid  = threadIdx.x;
  const int lane = tid & 31, warp = tid >> 5;
  const int a0   = blockIdx.x * 4;
  const int b    = a0 / APER;
  const int nbase = b * NPER;

  __shared__ __align__(16) float qk_s [4][H];
  __shared__ __align__(16) float qek_s[4][HE];
  __shared__ __align__(16) float dist_s[4][NPER];
  __shared__ __align__(16) float logit_s[4][NPER];
  __shared__ float ax_s[4][3];
  __shared__ float qbk_s[4];
  __shared__ int   list_s[NPER];
  __shared__ int   cnt_s;
  __shared__ float red_s[16];

  if (tid == 0) cnt_s = 0;
  for (int i = tid; i < 4*320; i += 512){
    int r = i / 320, c = i - r*320;
    float v = qke[(size_t)(a0 + r)*320 + c];
    if (c < 256) qk_s[r][c] = v; else qek_s[r][c-256] = v;
  }
  if (tid < 12) ax_s[tid/3][tid%3] = anchor_x[(size_t)(a0 + tid/3)*3 + (tid%3)];
  __syncthreads();

  // ---- Phase A: distances, zero logits, masked-node compaction ---------------
  {
    const int n = tid, ng = nbase + n;
    const float x0 = node_x[(size_t)3*ng+0];
    const float x1 = node_x[(size_t)3*ng+1];
    const float x2 = node_x[(size_t)3*ng+2];
#pragma unroll
    for (int a=0;a<4;a++){
      float dx = ax_s[a][0]-x0+EPSF;
      float dy = ax_s[a][1]-x1+EPSF;
      float dz = ax_s[a][2]-x2+EPSF;
      dist_s[a][n] = sqrtf(dx*dx + dy*dy + dz*dz);
      logit_s[a][n] = 0.0f;
    }
    if (nmask[ng] == 0.0f){
      int p = atomicAdd(&cnt_s, 1);
      list_s[p] = n;
    }
  }
  // qbk[a] = afeat[a] . wqbk + bqbk
  if (warp < 4){
    const float* ar = afeat + (size_t)(a0 + warp)*H;
    float s = 0.f;
#pragma unroll
    for (int kk=0;kk<8;kk++) s = fmaf(ar[lane + kk*32], aux[lane + kk*32], s);
    s = warp_reduce_sum(s);
    if (lane == 0) qbk_s[warp] = s + aux[576];
  }
  __syncthreads();

  // ---- Phase A2: logits for masked nodes only --------------------------------
  {
    const int cnt = cnt_s;
    const float mu0 = (float)lane * MU_STEP;
    const float mu1 = (float)(lane+32) * MU_STEP;
    for (int i = warp; i < cnt; i += 16){
      const int n = list_s[i], ng = nbase + n;
      const float4* nf4 = (const float4*)(nf + (size_t)ng*H);
      float4 u0 = nf4[lane], u1 = nf4[lane+32];
#pragma unroll
      for (int a=0;a<4;a++){
        float t = dist_s[a][n] * 0.1f;
        float z0 = (t - mu0) * INV_SIG, z1 = (t - mu1) * INV_SIG;
        float z0s = z0*z0, z1s = z1*z1;
        float acc = 0.f;
        if (z0s < 64.f) acc  = __expf(-z0s) * qek_s[a][lane];
        if (z1s < 64.f) acc += __expf(-z1s) * qek_s[a][lane+32];
        const float4* qa = (const float4*)qk_s[a];
        float4 q0 = qa[lane], q1 = qa[lane+32];
        acc = fmaf(u0.x,q0.x, fmaf(u0.y,q0.y, fmaf(u0.z,q0.z, fmaf(u0.w,q0.w, acc))));
        acc = fmaf(u1.x,q1.x, fmaf(u1.y,q1.y, fmaf(u1.z,q1.z, fmaf(u1.w,q1.w, acc))));
        acc = warp_reduce_sum(acc);
        if (lane == 0) logit_s[a][n] = (acc + qbk_s[a]) * (-INFM);
      }
    }
  }
  __syncthreads();

  // ---- Phase B: softmax over 512 nodes per anchor -----------------------------
#pragma unroll
  for (int a=0;a<4;a++){
    float l = logit_s[a][tid];
    float wm = warp_reduce_max(l);
    __syncthreads();
    if (lane == 0) red_s[warp] = wm;
    __syncthreads();
    float mx = red_s[0];
#pragma unroll
    for (int k=1;k<16;k++) mx = fmaxf(mx, red_s[k]);
    float e = __expf(l - mx);
    float ws = warp_reduce_sum(e);
    __syncthreads();
    if (lane == 0) red_s[warp] = ws;
    __syncthreads();
    float sm = red_s[0];
#pragma unroll
    for (int k=1;k<16;k++) sm += red_s[k];
    logit_s[a][tid] = e / sm;
  }
  __syncthreads();

  // ---- Phase C1: s[a][j] = sum_n attn * rbf -----------------------------------
  {
    const int a = tid >> 7, r = tid & 127, j = r >> 1, half = r & 1;
    const float mu = (float)j * MU_STEP;
    float acc = 0.f;
    const int nb0 = half * 256;
#pragma unroll 4
    for (int nn=0; nn<256; nn++){
      int n = nb0 + nn;
      float z = (dist_s[a][n]*0.1f - mu) * INV_SIG;
      float z2 = z*z;
      if (z2 < 60.f) acc = fmaf(logit_s[a][n], __expf(-z2), acc);
    }
    acc += __shfl_xor_sync(0xffffffffu, acc, 1);
    if (half == 0) cbuf[(size_t)(a0+a)*320 + 256 + j] = acc;
  }
  __syncthreads();

  // ---- Phase C2: n_tilde[a][i] = sum_n attn * nf[n][i] ------------------------
  {
    const int i = tid & 255, g = tid >> 8;
    float ac0=0.f, ac1=0.f, ac2=0.f, ac3=0.f;
    const float* nfb = nf + (size_t)(nbase + g*256)*H + i;
    const int nb0 = g*256;
    for (int nn=0; nn<256; nn+=4){
      float4 w0 = *(const float4*)&logit_s[0][nb0+nn];
      float4 w1 = *(const float4*)&logit_s[1][nb0+nn];
      float4 w2 = *(const float4*)&logit_s[2][nb0+nn];
      float4 w3 = *(const float4*)&logit_s[3][nb0+nn];
      float f0 = nfb[(size_t)(nn+0)*H];
      float f1 = nfb[(size_t)(nn+1)*H];
      float f2 = nfb[(size_t)(nn+2)*H];
      float f3 = nfb[(size_t)(nn+3)*H];
      ac0 = fmaf(w0.x,f0, fmaf(w0.y,f1, fmaf(w0.z,f2, fmaf(w0.w,f3, ac0))));
      ac1 = fmaf(w1.x,f0, fmaf(w1.y,f1, fmaf(w1.z,f2, fmaf(w1.w,f3, ac1))));
      ac2 = fmaf(w2.x,f0, fmaf(w2.y,f1, fmaf(w2.z,f2, fmaf(w2.w,f3, ac2))));
      ac3 = fmaf(w3.x,f0, fmaf(w3.y,f1, fmaf(w3.z,f2, fmaf(w3.w,f3, ac3))));
    }
    __syncthreads();
    if (g == 1){
      dist_s[0][i]=ac0; dist_s[1][i]=ac1; dist_s[2][i]=ac2; dist_s[3][i]=ac3;
    }
    __syncthreads();
    if (g == 0){
      cbuf[(size_t)(a0+0)*320 + i] = ac0 + dist_s[0][i];
      cbuf[(size_t)(a0+1)*320 + i] = ac1 + dist_s[1][i];
      cbuf[(size_t)(a0+2)*320 + i] = ac2 + dist_s[2][i];
      cbuf[(size_t)(a0+3)*320 + i] = ac3 + dist_s[3][i];
    }
  }
}

// ------------------------- residual + LayerNorm -------------------------------
__global__ void ln_kernel(const float* __restrict__ r,
                          const float* __restrict__ y1,
                          const float* __restrict__ g,
                          const float* __restrict__ bb,
                          float* __restrict__ out)
{
  __shared__ float red[8];
  const int row = blockIdx.x, t = threadIdx.x, lane = t & 31, w = t >> 5;
  const size_t o = (size_t)row*H + t;
  float x = r[o] + y1[o];
  float s = warp_reduce_sum(x);
  if (lane == 0) red[w] = s;
  __syncthreads();
  float mean = (red[0]+red[1]+red[2]+red[3]+red[4]+red[5]+red[6]+red[7]) * (1.f/H);
  float d = x - mean;
  float s2 = warp_reduce_sum(d*d);
  __syncthreads();
  if (lane == 0) red[w] = s2;
  __syncthreads();
  float var = (red[0]+red[1]+red[2]+red[3]+red[4]+red[5]+red[6]+red[7]) * (1.f/H);
  out[o] = d * rsqrtf(var + 1e-5f) * g[t] + bb[t];
}

// ------------------------- launch ---------------------------------------------
extern "C" void kernel_launch(void* const* d_in, const int* in_sizes, int n_in,
                              void* d_out, int out_size)
{
  const float* anchor_x        = (const float*)d_in[0];
  const float* node_x          = (const float*)d_in[1];
  const float* anchor_features = (const float*)d_in[2];
  const float* node_features   = (const float*)d_in[3];
  const float* node_mask       = (const float*)d_in[6];
  const float* Wq              = (const float*)d_in[7];
  const float* bq              = (const float*)d_in[8];
  const float* Wkv             = (const float*)d_in[9];
  const float* bkv             = (const float*)d_in[10];
  const float* ln1_g           = (const float*)d_in[11];
  const float* ln1_b           = (const float*)d_in[12];
  const float* W1              = (const float*)d_in[13];
  const float* b1              = (const float*)d_in[14];
  const float* W2              = (const float*)d_in[15];
  const float* b2              = (const float*)d_in[16];
  const float* W3              = (const float*)d_in[17];
  const float* b3              = (const float*)d_in[18];
  const float* ln2_g           = (const float*)d_in[19];
  const float* ln2_b           = (const float*)d_in[20];
  float* out = (float*)d_out;

  float *pwc, *paux, *pqke, *pcb, *pupd, *paf, *pm1, *pm2, *pm3;
  cudaGetSymbolAddress((void**)&pwc,  g_wc);
  cudaGetSymbolAddress((void**)&paux, g_aux);
  cudaGetSymbolAddress((void**)&pqke, g_qke);
  cudaGetSymbolAddress((void**)&pcb,  g_cb);
  cudaGetSymbolAddress((void**)&pupd, g_upd);
  cudaGetSymbolAddress((void**)&paf,  g_af);
  cudaGetSymbolAddress((void**)&pm1,  g_m1);
  cudaGetSymbolAddress((void**)&pm2,  g_m2);
  cudaGetSymbolAddress((void**)&pm3,  g_m3);

  // 1) Wc = Wq^T @ Wkv[:, :320]  (+ aux vectors in the spare block column)
  gemm2<16,true,true,false,false,true><<<dim3(6,16), 128>>>(
      Wq, 256, Wkv, 320, nullptr, pwc, 320, 256, 320, 256, bq, bkv, paux);

  // 2) qke = anchor_features @ Wc + biasc       (512 x 320, K=256)
  gemm2<16,false,true,true,false,false><<<dim3(5,32), 128>>>(
      anchor_features, 256, pwc, 320, paux + 256, pqke, 320, 512, 320, 256,
      nullptr, nullptr, nullptr);

  // 3) fused attention -> cbuf = [n_tilde | s]
  attn_kernel<<<128, 512>>>(anchor_x, node_x, node_mask, node_features,
                            anchor_features, paux, pqke, pcb);

  // 4) upd = cbuf @ Wkv[256:512,:].T + bkv[256:]  (512 x 256, K=320)
  gemm2<16,false,false,true,false,false><<<dim3(4,32), 128>>>(
      pcb, 320, Wkv + (size_t)256*320, 320, bkv + 256, pupd, 256, 512, 256, 320,
      nullptr, nullptr, nullptr);

  // 5) af = LN1(anchor_features + upd)
  ln_kernel<<<512, 256>>>(anchor_features, pupd, ln1_g, ln1_b, paf);

  // 6) m1 = relu(af @ W1.T + b1)                 (512 x 512, K=256)
  gemm2<16,false,false,true,true,false><<<dim3(8,32), 128>>>(
      paf, 256, W1, 256, b1, pm1, 512, 512, 512, 256,
      nullptr, nullptr, nullptr);

  // 7) m2 = relu(m1 @ W2.T + b2)                 (512 x 512, K=512)
  gemm2<16,false,false,true,true,false><<<dim3(8,32), 128>>>(
      pm1, 512, W2, 512, b2, pm2, 512, 512, 512, 512,
      nullptr, nullptr, nullptr);

  // 8) m3 = m2 @ W3.T + b3                       (512 x 256, K=512)
  gemm2<16,false,false,true,false,false><<<dim3(4,32), 128>>>(
      pm2, 512, W3, 512, b3, pm3, 256, 512, 256, 512,
      nullptr, nullptr, nullptr);

  // 9) out = LN2(af + m3)
  ln_kernel<<<512, 256>>>(paf, pm3, ln2_g, ln2_b, out);
}

// round 6
// speedup vs baseline: 1.3762x; 1.3738x over previous
#include <cuda_runtime.h>
#include <math.h>

#define NBLK 128
#define NTHR 256
#define H    256
#define HE   64
#define APER 64
#define NPER 512
#define EPSF 1e-8f
#define INFM 1000000.0f
#define MU_STEP (20.0f/63.0f)
#define INV_SIG (64.0f/20.0f)

// ------------------------- scratch (device globals) --------------------------
__device__ float g_wc [256*320];     // Wq^T @ Wkv[:, :320]
__device__ float g_aux[640];         // [0:256) wqbk, [256:576) biasc, [576] bq.bk
__device__ float g_qke[512*320];
__device__ float g_cb [512*320];     // [n_tilde | s]
__device__ float g_upd[2*512*256];   // split-K partials
__device__ float g_af [512*256];
__device__ float g_m1 [512*512];
__device__ float g_m2 [512*512];
__device__ float g_m3 [2*512*256];   // split-K partials

__device__ unsigned g_bar_count = 0;
__device__ unsigned g_bar_epoch = 0;

// ------------------------- shared structs ------------------------------------
struct GemmSmem { float As[2][16][40]; float Bs[2][16][68]; };
struct AttnSmem {
  float qk[4][H];
  float qek[4][HE];
  float dist[4][NPER];
  float logit[4][NPER];
  float ax[4][3];
  float qbk[4];
  int   list[NPER];
  int   cnt;
  float red[8];
};

// ------------------------- utils ---------------------------------------------
__device__ __forceinline__ float warp_reduce_sum(float v){
#pragma unroll
  for (int o=16;o>0;o>>=1) v += __shfl_xor_sync(0xffffffffu, v, o);
  return v;
}
__device__ __forceinline__ float warp_reduce_max(float v){
#pragma unroll
  for (int o=16;o>0;o>>=1) v = fmaxf(v, __shfl_xor_sync(0xffffffffu, v, o));
  return v;
}

// Software grid barrier. All NBLK blocks are co-resident (NBLK <= SM count),
// so spinning is safe. Epoch is monotonic across graph replays; count returns
// to zero at every barrier, so state is consistent at each launch boundary.
__device__ __forceinline__ void grid_barrier(){
  __syncthreads();
  if (threadIdx.x == 0){
    __threadfence();
    unsigned e = atomicAdd(&g_bar_epoch, 0u);
    unsigned prev = atomicAdd(&g_bar_count, 1u);
    if (prev == gridDim.x - 1){
      atomicExch(&g_bar_count, 0u);
      __threadfence();
      atomicAdd(&g_bar_epoch, 1u);
    } else {
      volatile unsigned* ep = (volatile unsigned*)&g_bar_epoch;
      while (*ep == e) { }
      __threadfence();
    }
  }
  __syncthreads();
}

// ------------------------- GEMM tile (TM x 64), 256 threads ------------------
// A_KM: A is K-major (A[k*lda+m]); else row-major (A[m*lda+k]).
// B_KN: B is (K,N) row-major; else (N,K) row-major (i.e. @ W.T).
template<int TM, bool A_KM, bool B_KN, bool BIAS, bool RELU>
__device__ void gemm_tile(const float* __restrict__ A, int lda,
                          const float* __restrict__ B, int ldb,
                          const float* __restrict__ bias,
                          float* __restrict__ C, int ldc,
                          int m0, int n0, int kbeg, int kend,
                          GemmSmem* sm)
{
  constexpr int RM = TM/16;
  const int tid = threadIdx.x;
  const int tx = tid & 15, ty = tid >> 4;

  // A-chunk load indices
  bool a_act; int a_i0, a_i1;
  if (A_KM){ constexpr int AM4 = TM/4;
    a_act = (tid < 16*AM4); a_i0 = tid / AM4; a_i1 = tid % AM4;      // k-row, m-grp
  } else {
    a_act = (tid < TM*4);   a_i0 = tid >> 2;  a_i1 = tid & 3;        // m-row, k-grp
  }
  // B-chunk load indices (16 x 64 = 256 float4, one per thread)
  int b_i0, b_i1;
  if (B_KN){ b_i0 = tid >> 4; b_i1 = tid & 15; }   // k-row, n-grp
  else     { b_i0 = tid >> 2; b_i1 = tid & 3;  }   // n-row, k-grp

  auto loadA = [&](int k0)->float4 {
    if (!a_act) return make_float4(0.f,0.f,0.f,0.f);
    if (A_KM) return *(const float4*)(A + (size_t)(k0 + a_i0)*lda + m0 + a_i1*4);
    else      return *(const float4*)(A + (size_t)(m0 + a_i0)*lda + k0 + a_i1*4);
  };
  auto loadB = [&](int k0)->float4 {
    if (B_KN) return *(const float4*)(B + (size_t)(k0 + b_i0)*ldb + n0 + b_i1*4);
    else      return *(const float4*)(B + (size_t)(n0 + b_i0)*ldb + k0 + b_i1*4);
  };
  auto storeA = [&](int buf, float4 v){
    if (!a_act) return;
    if (A_KM) *(float4*)&sm->As[buf][a_i0][a_i1*4] = v;
    else {
      sm->As[buf][a_i1*4+0][a_i0] = v.x;
      sm->As[buf][a_i1*4+1][a_i0] = v.y;
      sm->As[buf][a_i1*4+2][a_i0] = v.z;
      sm->As[buf][a_i1*4+3][a_i0] = v.w;
    }
  };
  auto storeB = [&](int buf, float4 v){
    if (B_KN) *(float4*)&sm->Bs[buf][b_i0][b_i1*4] = v;
    else {
      sm->Bs[buf][b_i1*4+0][b_i0] = v.x;
      sm->Bs[buf][b_i1*4+1][b_i0] = v.y;
      sm->Bs[buf][b_i1*4+2][b_i0] = v.z;
      sm->Bs[buf][b_i1*4+3][b_i0] = v.w;
    }
  };

  float acc[RM][4];
#pragma unroll
  for (int i=0;i<RM;i++)
#pragma unroll
    for (int j=0;j<4;j++) acc[i][j] = 0.f;

  __syncthreads();                       // protect smem from prior use
  storeA(0, loadA(kbeg));
  storeB(0, loadB(kbeg));
  __syncthreads();

  int buf = 0;
  for (int k0 = kbeg + 16; ; k0 += 16, buf ^= 1){
    const bool more = (k0 < kend);
    float4 pa, pb;
    if (more){ pa = loadA(k0); pb = loadB(k0); }
#pragma unroll
    for (int kk = 0; kk < 16; kk++){
      float4 bv = *(const float4*)&sm->Bs[buf][kk][tx*4];
#pragma unroll
      for (int i=0;i<RM;i++){
        float a = sm->As[buf][kk][ty*RM + i];
        acc[i][0] = fmaf(a, bv.x, acc[i][0]);
        acc[i][1] = fmaf(a, bv.y, acc[i][1]);
        acc[i][2] = fmaf(a, bv.z, acc[i][2]);
        acc[i][3] = fmaf(a, bv.w, acc[i][3]);
      }
    }
    if (!more) break;
    storeA(buf^1, pa);
    storeB(buf^1, pb);
    __syncthreads();
  }

#pragma unroll
  for (int i=0;i<RM;i++){
    const int m = m0 + ty*RM + i;
    float4 v = make_float4(acc[i][0], acc[i][1], acc[i][2], acc[i][3]);
    if (BIAS){
      float4 bb = *(const float4*)(bias + n0 + tx*4);
      v.x += bb.x; v.y += bb.y; v.z += bb.z; v.w += bb.w;
    }
    if (RELU){
      v.x = fmaxf(v.x,0.f); v.y = fmaxf(v.y,0.f);
      v.z = fmaxf(v.z,0.f); v.w = fmaxf(v.w,0.f);
    }
    *(float4*)(C + (size_t)m*ldc + n0 + tx*4) = v;
  }
}

// ------------------------- residual + LayerNorm (4 rows/block) ---------------
__device__ void ln4(const float* __restrict__ r,
                    const float* __restrict__ p0,
                    const float* __restrict__ p1,      // nullable
                    const float* __restrict__ bias,    // nullable
                    const float* __restrict__ g,
                    const float* __restrict__ b,
                    float* __restrict__ o)
{
  const int warp = threadIdx.x >> 5, lane = threadIdx.x & 31;
  if (warp >= 4) return;
  const size_t row = (size_t)blockIdx.x*4 + warp;
  float v[8]; float s = 0.f;
#pragma unroll
  for (int i=0;i<8;i++){
    int c = lane + i*32;
    float x = r[row*H+c] + p0[row*H+c];
    if (p1)   x += p1[row*H+c];
    if (bias) x += bias[c];
    v[i] = x; s += x;
  }
  s = warp_reduce_sum(s);
  float mean = s * (1.f/H);
  float s2 = 0.f;
#pragma unroll
  for (int i=0;i<8;i++){ float d = v[i]-mean; s2 += d*d; }
  s2 = warp_reduce_sum(s2);
  float inv = rsqrtf(s2*(1.f/H) + 1e-5f);
#pragma unroll
  for (int i=0;i<8;i++){
    int c = lane + i*32;
    o[row*H+c] = (v[i]-mean)*inv*g[c] + b[c];
  }
}

// ------------------------- megakernel ----------------------------------------
__global__ __launch_bounds__(NTHR)
void mega(const float* __restrict__ anchor_x,
          const float* __restrict__ node_x,
          const float* __restrict__ afeat,
          const float* __restrict__ nf,
          const float* __restrict__ nmask,
          const float* __restrict__ Wq,  const float* __restrict__ bq,
          const float* __restrict__ Wkv, const float* __restrict__ bkv,
          const float* __restrict__ ln1g, const float* __restrict__ ln1b,
          const float* __restrict__ W1, const float* __restrict__ b1,
          const float* __restrict__ W2, const float* __restrict__ b2,
          const float* __restrict__ W3, const float* __restrict__ b3,
          const float* __restrict__ ln2g, const float* __restrict__ ln2b,
          float* __restrict__ out)
{
  __shared__ GemmSmem sg;
  __shared__ AttnSmem sa;
  const int tid = threadIdx.x, bid = blockIdx.x;
  const int lane = tid & 31, warp = tid >> 5;

  // ========== stage A: wc = Wq^T @ Wkv[:, :320]  +  aux vectors ==============
  if (bid < 80){                                  // 16x5 tiles of 16x64
    int my = bid / 5, nx = bid % 5;
    gemm_tile<16,true,true,false,false>(Wq,256, Wkv,320, nullptr,
        g_wc,320, my*16, nx*64, 0,256, &sg);
  } else if (bid == 80){
    for (int i = tid; i < 256; i += NTHR){
      float s = 0.f;
      for (int j = 0; j < 256; j++) s = fmaf(Wq[(size_t)j*256 + i], bkv[j], s);
      g_aux[i] = s;                               // wqbk
    }
  } else if (bid == 81){
    for (int c = tid; c < 320; c += NTHR){
      float s = 0.f;
      for (int j = 0; j < 256; j++) s = fmaf(bq[j], Wkv[(size_t)j*320 + c], s);
      g_aux[256 + c] = s;                         // biasc
    }
  } else if (bid == 82){
    if (tid == 0){
      float s = 0.f;
      for (int j = 0; j < 256; j++) s = fmaf(bq[j], bkv[j], s);
      g_aux[576] = s;                             // bq.bk
    }
  }
  grid_barrier();

  // ========== stage B: attn prep (smem) + qke GEMM ===========================
  const int a0 = bid*4;
  const int nbase = (a0 / APER) * NPER;

  if (tid == 0) sa.cnt = 0;
  if (tid < 12) sa.ax[tid/3][tid%3] = anchor_x[(size_t)(a0 + tid/3)*3 + (tid%3)];
  __syncthreads();
#pragma unroll
  for (int rep = 0; rep < 2; rep++){
    const int n = tid + rep*256, ng = nbase + n;
    const float x0 = node_x[(size_t)3*ng+0];
    const float x1 = node_x[(size_t)3*ng+1];
    const float x2 = node_x[(size_t)3*ng+2];
#pragma unroll
    for (int a=0;a<4;a++){
      float dx = sa.ax[a][0]-x0+EPSF;
      float dy = sa.ax[a][1]-x1+EPSF;
      float dz = sa.ax[a][2]-x2+EPSF;
      sa.dist[a][n] = sqrtf(dx*dx + dy*dy + dz*dz);
      sa.logit[a][n] = 0.f;
    }
    if (nmask[ng] == 0.0f){
      int p = atomicAdd(&sa.cnt, 1);
      sa.list[p] = n;
    }
  }
  if (warp < 4){                                  // qbk[a] = af.wqbk + bq.bk
    const float* ar = afeat + (size_t)(a0 + warp)*H;
    float s = 0.f;
#pragma unroll
    for (int kk=0;kk<8;kk++) s = fmaf(ar[lane+kk*32], g_aux[lane+kk*32], s);
    s = warp_reduce_sum(s);
    if (lane == 0) sa.qbk[warp] = s + g_aux[576];
  }
  __syncthreads();

  if (bid < 80){                                  // qke: 16x5 tiles of 32x64
    int my = bid / 5, nx = bid % 5;
    gemm_tile<32,false,true,true,false>(afeat,256, g_wc,320, g_aux+256,
        g_qke,320, my*32, nx*64, 0,256, &sg);
  }
  grid_barrier();

  // ========== stage C: attention ============================================
  for (int i = tid; i < 4*320; i += NTHR){
    int r = i / 320, c = i - r*320;
    float v = g_qke[(size_t)(a0 + r)*320 + c];
    if (c < 256) sa.qk[r][c] = v; else sa.qek[r][c-256] = v;
  }
  __syncthreads();

  {                                               // masked logits, warp/node
    const int cnt = sa.cnt;
    const float mu0 = (float)lane * MU_STEP;
    const float mu1 = (float)(lane+32) * MU_STEP;
    for (int i = warp; i < cnt; i += 8){
      const int n = sa.list[i], ng = nbase + n;
      const float4* nf4 = (const float4*)(nf + (size_t)ng*H);
      float4 u0 = nf4[lane], u1 = nf4[lane+32];
#pragma unroll
      for (int a=0;a<4;a++){
        float t = sa.dist[a][n] * 0.1f;
        float z0 = (t - mu0)*INV_SIG, z1 = (t - mu1)*INV_SIG;
        float z0s = z0*z0, z1s = z1*z1;
        float acc = 0.f;
        if (z0s < 64.f) acc  = __expf(-z0s) * sa.qek[a][lane];
        if (z1s < 64.f) acc += __expf(-z1s) * sa.qek[a][lane+32];
        const float4* qa = (const float4*)sa.qk[a];
        float4 q0 = qa[lane], q1 = qa[lane+32];
        acc = fmaf(u0.x,q0.x, fmaf(u0.y,q0.y, fmaf(u0.z,q0.z, fmaf(u0.w,q0.w, acc))));
        acc = fmaf(u1.x,q1.x, fmaf(u1.y,q1.y, fmaf(u1.z,q1.z, fmaf(u1.w,q1.w, acc))));
        acc = warp_reduce_sum(acc);
        if (lane == 0) sa.logit[a][n] = (acc + sa.qbk[a]) * (-INFM);
      }
    }
  }
  __syncthreads();

#pragma unroll
  for (int a=0;a<4;a++){                          // softmax over 512
    float l0 = sa.logit[a][tid], l1 = sa.logit[a][tid+256];
    float m = warp_reduce_max(fmaxf(l0, l1));
    if (lane == 0) sa.red[warp] = m;
    __syncthreads();
    float mx = sa.red[0];
#pragma unroll
    for (int k=1;k<8;k++) mx = fmaxf(mx, sa.red[k]);
    float e0 = __expf(l0 - mx), e1 = __expf(l1 - mx);
    float s = warp_reduce_sum(e0 + e1);
    __syncthreads();
    if (lane == 0) sa.red[warp] = s;
    __syncthreads();
    float sm = 0.f;
#pragma unroll
    for (int k=0;k<8;k++) sm += sa.red[k];
    float inv = 1.f / sm;
    sa.logit[a][tid]     = e0 * inv;
    sa.logit[a][tid+256] = e1 * inv;
    __syncthreads();
  }

  {                                               // C1: s[a][j] = sum attn*rbf
    const int a = tid >> 6, j = tid & 63;
    const float mu = (float)j * MU_STEP;
    float acc = 0.f;
#pragma unroll 4
    for (int n=0;n<NPER;n++){
      float z = (sa.dist[a][n]*0.1f - mu) * INV_SIG;
      float z2 = z*z;
      if (z2 < 60.f) acc = fmaf(sa.logit[a][n], __expf(-z2), acc);
    }
    g_cb[(size_t)(a0+a)*320 + 256 + j] = acc;
  }
  __syncthreads();

  {                                               // C2: n_tilde = attn @ nf
    const int gg = tid >> 7, r = tid & 127;
    float ax0=0.f, ay0=0.f, ax1=0.f, ay1=0.f, ax2=0.f, ay2=0.f, ax3=0.f, ay3=0.f;
    const float* base = nf + (size_t)(nbase + gg*256)*H + 2*r;
    const int nb0 = gg*256;
    for (int nn=0;nn<256;nn++){
      float2 f = *(const float2*)(base + (size_t)nn*H);
      float w0 = sa.logit[0][nb0+nn];
      float w1 = sa.logit[1][nb0+nn];
      float w2 = sa.logit[2][nb0+nn];
      float w3 = sa.logit[3][nb0+nn];
      ax0 = fmaf(w0, f.x, ax0); ay0 = fmaf(w0, f.y, ay0);
      ax1 = fmaf(w1, f.x, ax1); ay1 = fmaf(w1, f.y, ay1);
      ax2 = fmaf(w2, f.x, ax2); ay2 = fmaf(w2, f.y, ay2);
      ax3 = fmaf(w3, f.x, ax3); ay3 = fmaf(w3, f.y, ay3);
    }
    __syncthreads();
    if (gg == 1){
      sa.dist[0][2*r] = ax0; sa.dist[0][2*r+1] = ay0;
      sa.dist[1][2*r] = ax1; sa.dist[1][2*r+1] = ay1;
      sa.dist[2][2*r] = ax2; sa.dist[2][2*r+1] = ay2;
      sa.dist[3][2*r] = ax3; sa.dist[3][2*r+1] = ay3;
    }
    __syncthreads();
    if (gg == 0){
      g_cb[(size_t)(a0+0)*320 + 2*r]   = ax0 + sa.dist[0][2*r];
      g_cb[(size_t)(a0+0)*320 + 2*r+1] = ay0 + sa.dist[0][2*r+1];
      g_cb[(size_t)(a0+1)*320 + 2*r]   = ax1 + sa.dist[1][2*r];
      g_cb[(size_t)(a0+1)*320 + 2*r+1] = ay1 + sa.dist[1][2*r+1];
      g_cb[(size_t)(a0+2)*320 + 2*r]   = ax2 + sa.dist[2][2*r];
      g_cb[(size_t)(a0+2)*320 + 2*r+1] = ay2 + sa.dist[2][2*r+1];
      g_cb[(size_t)(a0+3)*320 + 2*r]   = ax3 + sa.dist[3][2*r];
      g_cb[(size_t)(a0+3)*320 + 2*r+1] = ay3 + sa.dist[3][2*r+1];
    }
  }
  grid_barrier();

  // ========== stage D: upd partials (split-K=2) ==============================
  {
    const int z = bid >> 6, tt = bid & 63;        // 2 x (16x4) instances
    const int my = tt >> 2, nx = tt & 3;
    gemm_tile<32,false,false,false,false>(g_cb,320, Wkv + (size_t)256*320,320,
        nullptr, g_upd + (size_t)z*512*256, 256,
        my*32, nx*64, z*160, z*160 + 160, &sg);
  }
  grid_barrier();

  // ========== stage E: af = LN1(afeat + upd0 + upd1 + bkv_v) =================
  ln4(afeat, g_upd, g_upd + (size_t)512*256, bkv + 256, ln1g, ln1b, g_af);
  grid_barrier();

  // ========== stage F: m1 = relu(af @ W1.T + b1) =============================
  {
    const int my = bid >> 3, nx = bid & 7;        // 16x8 tiles
    gemm_tile<32,false,false,true,true>(g_af,256, W1,256, b1,
        g_m1,512, my*32, nx*64, 0,256, &sg);
  }
  grid_barrier();

  // ========== stage G: m2 = relu(m1 @ W2.T + b2) =============================
  {
    const int my = bid >> 3, nx = bid & 7;        // 16x8 tiles
    gemm_tile<32,false,false,true,true>(g_m1,512, W2,512, b2,
        g_m2,512, my*32, nx*64, 0,512, &sg);
  }
  grid_barrier();

  // ========== stage H: m3 partials (split-K=2) ===============================
  {
    const int z = bid >> 6, tt = bid & 63;        // 2 x (16x4) instances
    const int my = tt >> 2, nx = tt & 3;
    gemm_tile<32,false,false,false,false>(g_m2,512, W3,512, nullptr,
        g_m3 + (size_t)z*512*256, 256,
        my*32, nx*64, z*256, z*256 + 256, &sg);
  }
  grid_barrier();

  // ========== stage I: out = LN2(af + m3a + m3b + b3) ========================
  ln4(g_af, g_m3, g_m3 + (size_t)512*256, b3, ln2g, ln2b, out);
}

// ------------------------- launch ---------------------------------------------
extern "C" void kernel_launch(void* const* d_in, const int* in_sizes, int n_in,
                              void* d_out, int out_size)
{
  const float* anchor_x        = (const float*)d_in[0];
  const float* node_x          = (const float*)d_in[1];
  const float* anchor_features = (const float*)d_in[2];
  const float* node_features   = (const float*)d_in[3];
  const float* node_mask       = (const float*)d_in[6];
  const float* Wq              = (const float*)d_in[7];
  const float* bq              = (const float*)d_in[8];
  const float* Wkv             = (const float*)d_in[9];
  const float* bkv             = (const float*)d_in[10];
  const float* ln1_g           = (const float*)d_in[11];
  const float* ln1_b           = (const float*)d_in[12];
  const float* W1              = (const float*)d_in[13];
  const float* b1              = (const float*)d_in[14];
  const float* W2              = (const float*)d_in[15];
  const float* b2              = (const float*)d_in[16];
  const float* W3              = (const float*)d_in[17];
  const float* b3              = (const float*)d_in[18];
  const float* ln2_g           = (const float*)d_in[19];
  const float* ln2_b           = (const float*)d_in[20];
  float* out = (float*)d_out;

  mega<<<NBLK, NTHR>>>(anchor_x, node_x, anchor_features, node_features,
                       node_mask, Wq, bq, Wkv, bkv, ln1_g, ln1_b,
                       W1, b1, W2, b2, W3, b3, ln2_g, ln2_b, out);
}